// round 15
// baseline (speedup 1.0000x reference)
#include <cuda_runtime.h>
#include <cstdint>

#define B      64
#define T      256
#define N_IN   128
#define N_HID  2048
#define NB     128            // persistent CTAs (1 per SM)
#define TILE_J 16             // columns of A per CTA
#define NTH    1024
#define OUT_HALF (B*T*N_HID)
#define SBW    64             // spike-bit words per batch

// SMEM layout (step kernel)
#define SM_AS_BYTES (N_HID*TILE_J*4)                 // 131072 (swizzled, 64B rows)
#define SM_W_OFF    SM_AS_BYTES
#define SM_W_BYTES  (N_IN*TILE_J*4)                  // 8192
#define SM_U2_OFF   (SM_W_OFF + SM_W_BYTES)
#define SM_U2_BYTES (NTH*16)                         // 16384 (U(st+2) stash)
#define SM_TOTAL    (SM_U2_OFF + SM_U2_BYTES)        // 155648

// ---------------- scratch ----------------
__device__ unsigned int g_sbits[2][B*SBW];           // double-buffered packed spikes
__device__ unsigned int g_arrive;                    // single arrival counter (PROVEN)
__device__ volatile unsigned int g_epoch;

// ---------------- init: reset barrier + zero initial spikes ----------------
__global__ void init_kernel() {
    int t = threadIdx.x;
    if (t == 0) { g_arrive = 0u; g_epoch = 0u; }
    for (int i = t; i < B*SBW; i += blockDim.x) g_sbits[0][i] = 0u;
}

#define ACC2(av) asm("add.rn.f32x2 %0, %0, %2;\n\t" \
                     "add.rn.f32x2 %1, %1, %3;"     \
                     : "+l"(acc01), "+l"(acc23) : "l"((av).x), "l"((av).y))

// sparse row-gather over one 32-row spike word (proven inner loop)
#define GW(wword, rbase) do {                                                      \
    unsigned w = (wword);                                                          \
    const int rb = (rbase);                                                        \
    if (w) {                                                                       \
        int i = __ffs((int)w) - 1; w &= w - 1u;                                    \
        int r = rb + i;                                                            \
        ulonglong2 av = *(const ulonglong2*)(Ab + (r << 6) + ((jg ^ ((r >> 1) & 3)) << 4)); \
        while (w) {                                                                \
            int i2 = __ffs((int)w) - 1; w &= w - 1u;                               \
            int r2 = rb + i2;                                                      \
            ulonglong2 av2 = *(const ulonglong2*)(Ab + (r2 << 6) + ((jg ^ ((r2 >> 1) & 3)) << 4)); \
            ACC2(av);                                                              \
            av = av2;                                                              \
        }                                                                          \
        ACC2(av);                                                                  \
    }                                                                              \
} while (0)

// ---------------- persistent step kernel ----------------
// CTA c owns cols [c*16, c*16+16).
// Thread map: warp wid owns 8 units; unit = wid*8 + (lane&7) = b*4 + jg,
// kq = lane>>3. Cross-quarter reduction = 3 shfl_down, fixed add order.
// R15 = R13 (proven barrier: single 128-way atomic, thread-0-only fences,
// volatile spin) + two reordering-only edits:
//  - spike words: all four uint4 loads issued upfront (one L2 latency for 16)
//  - epilogue: spike-word publish STG issued BEFORE the out[] stores
__global__ void __launch_bounds__(NTH, 1)
step_kernel(const float* __restrict__ x,
            const float* __restrict__ W_in,
            const float* __restrict__ A,
            const float* __restrict__ bias,
            const float* __restrict__ mem0,
            float* __restrict__ out) {
    extern __shared__ unsigned char smem_raw[];
    float*         As  = (float*)smem_raw;                   // swizzled [2048][16]
    float*         Ws  = (float*)(smem_raw + SM_W_OFF);      // [128][16]
    unsigned char* u2  = smem_raw + SM_U2_OFF;               // per-thread 16B stash

    const int c    = blockIdx.x;
    const int tid  = threadIdx.x;
    const int lane = tid & 31;
    const int wid  = tid >> 5;
    const int unit = wid*8 + (lane & 7);       // 0..255 = b*4 + jg
    const int jg   = unit & 3;
    const int b    = unit >> 2;
    const int kq   = lane >> 3;                // 0..3

    // A tile, swizzled: word(r,jj) -> r*16 + ((jj>>2 ^ ((r>>1)&3))<<2) + (jj&3)
    for (int idx = tid; idx < N_HID*TILE_J; idx += NTH) {
        int r = idx >> 4, jj = idx & 15;
        int d = (r << 4) + ((((jj >> 2) ^ ((r >> 1) & 3)) << 2)) + (jj & 3);
        As[d] = A[(size_t)r*N_HID + c*TILE_J + jj];
    }
    // W_in tile (plain [k][16])
    for (int idx = tid; idx < N_IN*TILE_J; idx += NTH) {
        int k = idx >> 4, jj = idx & 15;
        Ws[idx] = W_in[(size_t)k*N_HID + c*TILE_J + jj];
    }

    // epilogue persistent state (owner lanes: kq == 0, i.e. lane < 8)
    float4 mem = make_float4(0.f,0.f,0.f,0.f);
    float4 spk = make_float4(0.f,0.f,0.f,0.f);
    float4 biasv = make_float4(0.f,0.f,0.f,0.f);
    const int j0_e = c*TILE_J + jg*4;
    if (kq == 0) {
        mem   = *(const float4*)&mem0[(size_t)b*N_HID + j0_e];
        biasv = *(const float4*)&bias[j0_e];
    }
    __syncthreads();

    const unsigned char* Ab   = (const unsigned char*)As;
    const unsigned char* Wb   = (const unsigned char*)Ws + jg*16;
    unsigned char*       u2p  = u2 + tid*16;
    const int            srcq = lane & 28;     // quad base (same b,kq; jg 0-3)

    // ---- U-partial for step 0 (pre-loop, single step) ----
    unsigned long long acc01 = 0ull, acc23 = 0ull;
    {
        const float* xp = x + ((size_t)b*T + 0)*N_IN + kq*32 + jg*8;
        float xf[8];
        *(float4*)&xf[0] = *(const float4*)xp;
        *(float4*)&xf[4] = *(const float4*)(xp + 4);
        #pragma unroll
        for (int kk = 0; kk < 32; kk++) {
            float xv = __shfl_sync(0xffffffffu, xf[kk & 7], srcq | (kk >> 3), 32);
            ulonglong2 wv = *(const ulonglong2*)(Wb + (kq*32 + kk)*64);
            unsigned long long xx;
            asm("mov.b64 %0, {%1,%1};" : "=l"(xx) : "f"(xv));
            asm("fma.rn.f32x2 %0, %2, %3, %0;\n\t"
                "fma.rn.f32x2 %1, %2, %4, %1;"
                : "+l"(acc01), "+l"(acc23) : "l"(xx), "l"(wv.x), "l"(wv.y));
        }
    }

    for (int st = 0; st < T; st++) {
        // ---- spike words: all 4 uint4 loads upfront (one L2 latency for 16 words)
        const uint4* gw = (const uint4*)g_sbits[st & 1] + (b*16 + kq*4);
        uint4 w0 = __ldcg(gw);
        uint4 w1 = __ldcg(gw + 1);
        uint4 w2 = __ldcg(gw + 2);
        uint4 w3 = __ldcg(gw + 3);

        GW(w0.x, kq*512 + 0*32);  GW(w0.y, kq*512 + 1*32);
        GW(w0.z, kq*512 + 2*32);  GW(w0.w, kq*512 + 3*32);
        GW(w1.x, kq*512 + 4*32);  GW(w1.y, kq*512 + 5*32);
        GW(w1.z, kq*512 + 6*32);  GW(w1.w, kq*512 + 7*32);
        GW(w2.x, kq*512 + 8*32);  GW(w2.y, kq*512 + 9*32);
        GW(w2.z, kq*512 + 10*32); GW(w2.w, kq*512 + 11*32);
        GW(w3.x, kq*512 + 12*32); GW(w3.y, kq*512 + 13*32);
        GW(w3.z, kq*512 + 14*32); GW(w3.w, kq*512 + 15*32);

        // ---- cross-quarter reduction: in-warp shfl, fixed add order
        unsigned long long p01a = __shfl_down_sync(0xffffffffu, acc01, 8, 32);
        unsigned long long p23a = __shfl_down_sync(0xffffffffu, acc23, 8, 32);
        unsigned long long p01b = __shfl_down_sync(0xffffffffu, acc01, 16, 32);
        unsigned long long p23b = __shfl_down_sync(0xffffffffu, acc23, 16, 32);
        unsigned long long p01c = __shfl_down_sync(0xffffffffu, acc01, 24, 32);
        unsigned long long p23c = __shfl_down_sync(0xffffffffu, acc23, 24, 32);

        if (kq == 0) {
            asm("add.rn.f32x2 %0, %0, %1;" : "+l"(acc01) : "l"(p01a));
            asm("add.rn.f32x2 %0, %0, %1;" : "+l"(acc23) : "l"(p23a));
            asm("add.rn.f32x2 %0, %0, %1;" : "+l"(acc01) : "l"(p01b));
            asm("add.rn.f32x2 %0, %0, %1;" : "+l"(acc23) : "l"(p23b));
            asm("add.rn.f32x2 %0, %0, %1;" : "+l"(acc01) : "l"(p01c));
            asm("add.rn.f32x2 %0, %0, %1;" : "+l"(acc23) : "l"(p23c));

            float r0, r1, r2, r3;
            asm("mov.b64 {%0,%1}, %2;" : "=f"(r0), "=f"(r1) : "l"(acc01));
            asm("mov.b64 {%0,%1}, %2;" : "=f"(r2), "=f"(r3) : "l"(acc23));

            float4 y;
            y.x = tanhf(0.5f*r0 + 0.5f*biasv.x);
            y.y = tanhf(0.5f*r1 + 0.5f*biasv.y);
            y.z = tanhf(0.5f*r2 + 0.5f*biasv.z);
            y.w = tanhf(0.5f*r3 + 0.5f*biasv.w);

            mem.x = mem.x*0.5f - 0.5f*(1.0f - spk.x) + y.x;
            mem.y = mem.y*0.5f - 0.5f*(1.0f - spk.y) + y.y;
            mem.z = mem.z*0.5f - 0.5f*(1.0f - spk.z) + y.z;
            mem.w = mem.w*0.5f - 0.5f*(1.0f - spk.w) + y.w;

            spk.x = (mem.x > 0.5f) ? 1.0f : 0.0f;
            spk.y = (mem.y > 0.5f) ? 1.0f : 0.0f;
            spk.z = (mem.z > 0.5f) ? 1.0f : 0.0f;
            spk.w = (mem.w > 0.5f) ? 1.0f : 0.0f;

            // ---- publish FIRST (the only store consumers wait on)
            unsigned v = ((spk.x != 0.f ? 1u : 0u) | (spk.y != 0.f ? 2u : 0u)
                        | (spk.z != 0.f ? 4u : 0u) | (spk.w != 0.f ? 8u : 0u)) << (jg*4);
            v |= __shfl_xor_sync(0xFFu, v, 1, 32);
            v |= __shfl_xor_sync(0xFFu, v, 2, 32);
            if (jg == 0)
                ((unsigned short*)g_sbits[(st + 1) & 1])[(size_t)b*(N_HID/16) + c] =
                    (unsigned short)v;

            // ---- out stores drain off the critical path
            const size_t base = (size_t)(b*T + st)*N_HID + j0_e;
            *(float4*)&out[base]            = mem;
            *(float4*)&out[OUT_HALF + base] = spk;
        }

        // ---- grid barrier (PROVEN: single counter, thread-0-only fences)
        const unsigned target = (unsigned)(st + 1);
        __syncthreads();                       // publishes done CTA-wide
        if (tid == 0) {
            __threadfence();                   // release (cumulative via bar.sync)
            unsigned old = atomicAdd(&g_arrive, 1u);
            if ((old & (NB - 1u)) == (NB - 1u)) {
                __threadfence();
                g_epoch = target;              // volatile release store
            }
        }

        // ---- barrier slack: prepare U for next step(s) (proven batching)
        acc01 = 0ull; acc23 = 0ull;
        if (st + 1 < T) {
            if ((st & 1) == 0) {
                const bool do2 = (st + 2 < T);
                const float* xp1 = x + ((size_t)b*T + (st + 1))*N_IN + kq*32 + jg*8;
                const float* xp2 = x + ((size_t)b*T + (do2 ? st + 2 : st + 1))*N_IN + kq*32 + jg*8;
                float xf1[8], xf2[8];
                *(float4*)&xf1[0] = *(const float4*)xp1;
                *(float4*)&xf1[4] = *(const float4*)(xp1 + 4);
                *(float4*)&xf2[0] = *(const float4*)xp2;
                *(float4*)&xf2[4] = *(const float4*)(xp2 + 4);
                unsigned long long d01 = 0ull, d23 = 0ull;
                #pragma unroll
                for (int kk = 0; kk < 32; kk++) {
                    float xv1 = __shfl_sync(0xffffffffu, xf1[kk & 7], srcq | (kk >> 3), 32);
                    float xv2 = __shfl_sync(0xffffffffu, xf2[kk & 7], srcq | (kk >> 3), 32);
                    ulonglong2 wv = *(const ulonglong2*)(Wb + (kq*32 + kk)*64);
                    unsigned long long xx1, xx2;
                    asm("mov.b64 %0, {%1,%1};" : "=l"(xx1) : "f"(xv1));
                    asm("mov.b64 %0, {%1,%1};" : "=l"(xx2) : "f"(xv2));
                    asm("fma.rn.f32x2 %0, %2, %3, %0;\n\t"
                        "fma.rn.f32x2 %1, %2, %4, %1;"
                        : "+l"(acc01), "+l"(acc23) : "l"(xx1), "l"(wv.x), "l"(wv.y));
                    asm("fma.rn.f32x2 %0, %2, %3, %0;\n\t"
                        "fma.rn.f32x2 %1, %2, %4, %1;"
                        : "+l"(d01), "+l"(d23) : "l"(xx2), "l"(wv.x), "l"(wv.y));
                }
                if (do2) {
                    ulonglong2 v; v.x = d01; v.y = d23;
                    *(ulonglong2*)u2p = v;
                }
            } else {
                ulonglong2 v = *(const ulonglong2*)u2p;
                acc01 = v.x; acc23 = v.y;
            }
        }

        if (tid == 0) {
            while (g_epoch < target) { }       // volatile spin
            __threadfence();                   // acquire
        }
        __syncthreads();                       // propagate CTA-wide
    }
}

// ---------------- launch ----------------
extern "C" void kernel_launch(void* const* d_in, const int* in_sizes, int n_in,
                              void* d_out, int out_size) {
    const float* x    = (const float*)d_in[0];
    const float* W_in = (const float*)d_in[1];
    const float* A    = (const float*)d_in[2];
    const float* bias = (const float*)d_in[3];
    const float* mem0 = (const float*)d_in[4];
    float* out = (float*)d_out;

    cudaFuncSetAttribute(step_kernel, cudaFuncAttributeMaxDynamicSharedMemorySize,
                         SM_TOTAL);

    init_kernel<<<1, 256>>>();
    step_kernel<<<NB, NTH, SM_TOTAL>>>(x, W_in, A, bias, mem0, out);
}

// round 16
// speedup vs baseline: 1.5330x; 1.5330x over previous
#include <cuda_runtime.h>
#include <cstdint>

#define B      64
#define T      256
#define N_IN   128
#define N_HID  2048
#define NB     128            // persistent CTAs (1 per SM)
#define TILE_J 16             // columns of A per CTA
#define NTH    1024
#define OUT_HALF (B*T*N_HID)
#define SBW    64             // spike-bit words per batch

// SMEM layout (step kernel)
#define SM_AS_BYTES (N_HID*TILE_J*4)                 // 131072 (swizzled, 64B rows)
#define SM_W_OFF    SM_AS_BYTES
#define SM_W_BYTES  (N_IN*TILE_J*4)                  // 8192
#define SM_U2_OFF   (SM_W_OFF + SM_W_BYTES)
#define SM_U2_BYTES (NTH*16)                         // 16384 (U(st+2) stash)
#define SM_TOTAL    (SM_U2_OFF + SM_U2_BYTES)        // 155648

// ---------------- scratch ----------------
__device__ unsigned int g_sbits[2][B*SBW];           // double-buffered packed spikes
__device__ unsigned int g_arrive;                    // single arrival counter (PROVEN)
__device__ volatile unsigned int g_epoch;

// ---------------- init: reset barrier + zero initial spikes ----------------
__global__ void init_kernel() {
    int t = threadIdx.x;
    if (t == 0) { g_arrive = 0u; g_epoch = 0u; }
    for (int i = t; i < B*SBW; i += blockDim.x) g_sbits[0][i] = 0u;
}

#define ACC2(av) asm("add.rn.f32x2 %0, %0, %2;\n\t" \
                     "add.rn.f32x2 %1, %1, %3;"     \
                     : "+l"(acc01), "+l"(acc23) : "l"((av).x), "l"((av).y))

// sparse row-gather over one 32-row spike word (proven inner loop)
#define GW(wword, rbase) do {                                                      \
    unsigned w = (wword);                                                          \
    const int rb = (rbase);                                                        \
    if (w) {                                                                       \
        int i = __ffs((int)w) - 1; w &= w - 1u;                                    \
        int r = rb + i;                                                            \
        ulonglong2 av = *(const ulonglong2*)(Ab + (r << 6) + ((jg ^ ((r >> 1) & 3)) << 4)); \
        while (w) {                                                                \
            int i2 = __ffs((int)w) - 1; w &= w - 1u;                               \
            int r2 = rb + i2;                                                      \
            ulonglong2 av2 = *(const ulonglong2*)(Ab + (r2 << 6) + ((jg ^ ((r2 >> 1) & 3)) << 4)); \
            ACC2(av);                                                              \
            av = av2;                                                              \
        }                                                                          \
        ACC2(av);                                                                  \
    }                                                                              \
} while (0)

// ---------------- persistent step kernel ----------------
// CTA c owns cols [c*16, c*16+16).
// Thread map: warp wid owns 8 units; unit = wid*8 + (lane&7) = b*4 + jg,
// kq = lane>>3. Cross-quarter reduction = 3 shfl_down, fixed add order.
// R16 = R13 byte-for-byte (incl. the depth-1 wa/wb spike-load pipeline that
// keeps only 2 uint4 live — R15's 4-upfront variant spilled at the 64-reg cap
// and regressed 1382->2124) + ONE register-neutral edit: the spike-word
// publish STG (the only store consumers wait on) issues BEFORE the out[]
// stores, taking ~100 cyc off the inter-CTA release path.
__global__ void __launch_bounds__(NTH, 1)
step_kernel(const float* __restrict__ x,
            const float* __restrict__ W_in,
            const float* __restrict__ A,
            const float* __restrict__ bias,
            const float* __restrict__ mem0,
            float* __restrict__ out) {
    extern __shared__ unsigned char smem_raw[];
    float*         As  = (float*)smem_raw;                   // swizzled [2048][16]
    float*         Ws  = (float*)(smem_raw + SM_W_OFF);      // [128][16]
    unsigned char* u2  = smem_raw + SM_U2_OFF;               // per-thread 16B stash

    const int c    = blockIdx.x;
    const int tid  = threadIdx.x;
    const int lane = tid & 31;
    const int wid  = tid >> 5;
    const int unit = wid*8 + (lane & 7);       // 0..255 = b*4 + jg
    const int jg   = unit & 3;
    const int b    = unit >> 2;
    const int kq   = lane >> 3;                // 0..3

    // A tile, swizzled: word(r,jj) -> r*16 + ((jj>>2 ^ ((r>>1)&3))<<2) + (jj&3)
    for (int idx = tid; idx < N_HID*TILE_J; idx += NTH) {
        int r = idx >> 4, jj = idx & 15;
        int d = (r << 4) + ((((jj >> 2) ^ ((r >> 1) & 3)) << 2)) + (jj & 3);
        As[d] = A[(size_t)r*N_HID + c*TILE_J + jj];
    }
    // W_in tile (plain [k][16])
    for (int idx = tid; idx < N_IN*TILE_J; idx += NTH) {
        int k = idx >> 4, jj = idx & 15;
        Ws[idx] = W_in[(size_t)k*N_HID + c*TILE_J + jj];
    }

    // epilogue persistent state (owner lanes: kq == 0, i.e. lane < 8)
    float4 mem = make_float4(0.f,0.f,0.f,0.f);
    float4 spk = make_float4(0.f,0.f,0.f,0.f);
    float4 biasv = make_float4(0.f,0.f,0.f,0.f);
    const int j0_e = c*TILE_J + jg*4;
    if (kq == 0) {
        mem   = *(const float4*)&mem0[(size_t)b*N_HID + j0_e];
        biasv = *(const float4*)&bias[j0_e];
    }
    __syncthreads();

    const unsigned char* Ab   = (const unsigned char*)As;
    const unsigned char* Wb   = (const unsigned char*)Ws + jg*16;
    unsigned char*       u2p  = u2 + tid*16;
    const int            srcq = lane & 28;     // quad base (same b,kq; jg 0-3)

    // ---- U-partial for step 0 (pre-loop, single step) ----
    unsigned long long acc01 = 0ull, acc23 = 0ull;
    {
        const float* xp = x + ((size_t)b*T + 0)*N_IN + kq*32 + jg*8;
        float xf[8];
        *(float4*)&xf[0] = *(const float4*)xp;
        *(float4*)&xf[4] = *(const float4*)(xp + 4);
        #pragma unroll
        for (int kk = 0; kk < 32; kk++) {
            float xv = __shfl_sync(0xffffffffu, xf[kk & 7], srcq | (kk >> 3), 32);
            ulonglong2 wv = *(const ulonglong2*)(Wb + (kq*32 + kk)*64);
            unsigned long long xx;
            asm("mov.b64 %0, {%1,%1};" : "=l"(xx) : "f"(xv));
            asm("fma.rn.f32x2 %0, %2, %3, %0;\n\t"
                "fma.rn.f32x2 %1, %2, %4, %1;"
                : "+l"(acc01), "+l"(acc23) : "l"(xx), "l"(wv.x), "l"(wv.y));
        }
    }

    for (int st = 0; st < T; st++) {
        // ---- spike words: depth-1 pipelined gmem reads (R13-proven, 2 uint4 live)
        const uint4* gw = (const uint4*)g_sbits[st & 1] + (b*16 + kq*4);
        uint4 wa = __ldcg(gw);
        uint4 wb = __ldcg(gw + 1);

        GW(wa.x, kq*512 + 0*32);  GW(wa.y, kq*512 + 1*32);
        GW(wa.z, kq*512 + 2*32);  GW(wa.w, kq*512 + 3*32);
        wa = __ldcg(gw + 2);
        GW(wb.x, kq*512 + 4*32);  GW(wb.y, kq*512 + 5*32);
        GW(wb.z, kq*512 + 6*32);  GW(wb.w, kq*512 + 7*32);
        wb = __ldcg(gw + 3);
        GW(wa.x, kq*512 + 8*32);  GW(wa.y, kq*512 + 9*32);
        GW(wa.z, kq*512 + 10*32); GW(wa.w, kq*512 + 11*32);
        GW(wb.x, kq*512 + 12*32); GW(wb.y, kq*512 + 13*32);
        GW(wb.z, kq*512 + 14*32); GW(wb.w, kq*512 + 15*32);

        // ---- cross-quarter reduction: in-warp shfl, fixed add order
        unsigned long long p01a = __shfl_down_sync(0xffffffffu, acc01, 8, 32);
        unsigned long long p23a = __shfl_down_sync(0xffffffffu, acc23, 8, 32);
        unsigned long long p01b = __shfl_down_sync(0xffffffffu, acc01, 16, 32);
        unsigned long long p23b = __shfl_down_sync(0xffffffffu, acc23, 16, 32);
        unsigned long long p01c = __shfl_down_sync(0xffffffffu, acc01, 24, 32);
        unsigned long long p23c = __shfl_down_sync(0xffffffffu, acc23, 24, 32);

        if (kq == 0) {
            asm("add.rn.f32x2 %0, %0, %1;" : "+l"(acc01) : "l"(p01a));
            asm("add.rn.f32x2 %0, %0, %1;" : "+l"(acc23) : "l"(p23a));
            asm("add.rn.f32x2 %0, %0, %1;" : "+l"(acc01) : "l"(p01b));
            asm("add.rn.f32x2 %0, %0, %1;" : "+l"(acc23) : "l"(p23b));
            asm("add.rn.f32x2 %0, %0, %1;" : "+l"(acc01) : "l"(p01c));
            asm("add.rn.f32x2 %0, %0, %1;" : "+l"(acc23) : "l"(p23c));

            float r0, r1, r2, r3;
            asm("mov.b64 {%0,%1}, %2;" : "=f"(r0), "=f"(r1) : "l"(acc01));
            asm("mov.b64 {%0,%1}, %2;" : "=f"(r2), "=f"(r3) : "l"(acc23));

            float4 y;
            y.x = tanhf(0.5f*r0 + 0.5f*biasv.x);
            y.y = tanhf(0.5f*r1 + 0.5f*biasv.y);
            y.z = tanhf(0.5f*r2 + 0.5f*biasv.z);
            y.w = tanhf(0.5f*r3 + 0.5f*biasv.w);

            mem.x = mem.x*0.5f - 0.5f*(1.0f - spk.x) + y.x;
            mem.y = mem.y*0.5f - 0.5f*(1.0f - spk.y) + y.y;
            mem.z = mem.z*0.5f - 0.5f*(1.0f - spk.z) + y.z;
            mem.w = mem.w*0.5f - 0.5f*(1.0f - spk.w) + y.w;

            spk.x = (mem.x > 0.5f) ? 1.0f : 0.0f;
            spk.y = (mem.y > 0.5f) ? 1.0f : 0.0f;
            spk.z = (mem.z > 0.5f) ? 1.0f : 0.0f;
            spk.w = (mem.w > 0.5f) ? 1.0f : 0.0f;

            // ---- publish FIRST (the only store consumers wait on)
            unsigned v = ((spk.x != 0.f ? 1u : 0u) | (spk.y != 0.f ? 2u : 0u)
                        | (spk.z != 0.f ? 4u : 0u) | (spk.w != 0.f ? 8u : 0u)) << (jg*4);
            v |= __shfl_xor_sync(0xFFu, v, 1, 32);
            v |= __shfl_xor_sync(0xFFu, v, 2, 32);
            if (jg == 0)
                ((unsigned short*)g_sbits[(st + 1) & 1])[(size_t)b*(N_HID/16) + c] =
                    (unsigned short)v;

            // ---- out stores drain off the critical path
            const size_t base = (size_t)(b*T + st)*N_HID + j0_e;
            *(float4*)&out[base]            = mem;
            *(float4*)&out[OUT_HALF + base] = spk;
        }

        // ---- grid barrier (PROVEN: single counter, thread-0-only fences)
        const unsigned target = (unsigned)(st + 1);
        __syncthreads();                       // publishes done CTA-wide
        if (tid == 0) {
            __threadfence();                   // release (cumulative via bar.sync)
            unsigned old = atomicAdd(&g_arrive, 1u);
            if ((old & (NB - 1u)) == (NB - 1u)) {
                __threadfence();
                g_epoch = target;              // volatile release store
            }
        }

        // ---- barrier slack: prepare U for next step(s) (proven batching)
        acc01 = 0ull; acc23 = 0ull;
        if (st + 1 < T) {
            if ((st & 1) == 0) {
                const bool do2 = (st + 2 < T);
                const float* xp1 = x + ((size_t)b*T + (st + 1))*N_IN + kq*32 + jg*8;
                const float* xp2 = x + ((size_t)b*T + (do2 ? st + 2 : st + 1))*N_IN + kq*32 + jg*8;
                float xf1[8], xf2[8];
                *(float4*)&xf1[0] = *(const float4*)xp1;
                *(float4*)&xf1[4] = *(const float4*)(xp1 + 4);
                *(float4*)&xf2[0] = *(const float4*)xp2;
                *(float4*)&xf2[4] = *(const float4*)(xp2 + 4);
                unsigned long long d01 = 0ull, d23 = 0ull;
                #pragma unroll
                for (int kk = 0; kk < 32; kk++) {
                    float xv1 = __shfl_sync(0xffffffffu, xf1[kk & 7], srcq | (kk >> 3), 32);
                    float xv2 = __shfl_sync(0xffffffffu, xf2[kk & 7], srcq | (kk >> 3), 32);
                    ulonglong2 wv = *(const ulonglong2*)(Wb + (kq*32 + kk)*64);
                    unsigned long long xx1, xx2;
                    asm("mov.b64 %0, {%1,%1};" : "=l"(xx1) : "f"(xv1));
                    asm("mov.b64 %0, {%1,%1};" : "=l"(xx2) : "f"(xv2));
                    asm("fma.rn.f32x2 %0, %2, %3, %0;\n\t"
                        "fma.rn.f32x2 %1, %2, %4, %1;"
                        : "+l"(acc01), "+l"(acc23) : "l"(xx1), "l"(wv.x), "l"(wv.y));
                    asm("fma.rn.f32x2 %0, %2, %3, %0;\n\t"
                        "fma.rn.f32x2 %1, %2, %4, %1;"
                        : "+l"(d01), "+l"(d23) : "l"(xx2), "l"(wv.x), "l"(wv.y));
                }
                if (do2) {
                    ulonglong2 v; v.x = d01; v.y = d23;
                    *(ulonglong2*)u2p = v;
                }
            } else {
                ulonglong2 v = *(const ulonglong2*)u2p;
                acc01 = v.x; acc23 = v.y;
            }
        }

        if (tid == 0) {
            while (g_epoch < target) { }       // volatile spin
            __threadfence();                   // acquire
        }
        __syncthreads();                       // propagate CTA-wide
    }
}

// ---------------- launch ----------------
extern "C" void kernel_launch(void* const* d_in, const int* in_sizes, int n_in,
                              void* d_out, int out_size) {
    const float* x    = (const float*)d_in[0];
    const float* W_in = (const float*)d_in[1];
    const float* A    = (const float*)d_in[2];
    const float* bias = (const float*)d_in[3];
    const float* mem0 = (const float*)d_in[4];
    float* out = (float*)d_out;

    cudaFuncSetAttribute(step_kernel, cudaFuncAttributeMaxDynamicSharedMemorySize,
                         SM_TOTAL);

    init_kernel<<<1, 256>>>();
    step_kernel<<<NB, NTH, SM_TOTAL>>>(x, W_in, A, bias, mem0, out);
}